// round 1
// baseline (speedup 1.0000x reference)
#include <cuda_runtime.h>

#define B_    16
#define TRG_  512
#define SRC_  1024
#define ENC_  1024
#define TRGD_ 1024

// Scratch for H' = hidden @ W  (B*TRG x ENC) = 32 MB
__device__ float g_Hp[(long)B_ * TRG_ * ENC_];

// ---------------------------------------------------------------------------
// Tiled SGEMM: C[M,N] = A[M,K] @ B  (NT: B is row-major (N,K); NN: (K,N))
// Optional per-column mask multiply on the output (mask length N per batch z).
// BM=BN=128, BK=8, 8x8 per thread, 256 threads.
// ---------------------------------------------------------------------------
template<bool NT, bool MASKED>
__global__ __launch_bounds__(256)
void sgemm128(const float* __restrict__ Ag, const float* __restrict__ Bg,
              float* __restrict__ Cg, const float* __restrict__ maskg,
              int M, int N, int K,
              long sA, long sB, long sC, long sM)
{
    constexpr int BM = 128, BN = 128, BK = 8, TM = 8, TN = 8;
    __shared__ float As[BK][BM];
    __shared__ float Bs[BK][BN];

    const int bz = blockIdx.z;
    const float* A  = Ag + (long)bz * sA;
    const float* Bp = Bg + (long)bz * sB;
    float*       C  = Cg + (long)bz * sC;

    const int bm = blockIdx.y * BM;
    const int bn = blockIdx.x * BN;
    const int tid = threadIdx.x;
    const int tx = tid & 15;     // 0..15 -> N
    const int ty = tid >> 4;     // 0..15 -> M

    // A tile load mapping: one float4 per thread (128 m x 8 k)
    const int a_m = tid >> 1;
    const int a_k = (tid & 1) * 4;
    // B tile (NT): one float4 along K per thread (128 n x 8 k)
    const int bt_n = tid >> 1;
    const int bt_k = (tid & 1) * 4;
    // B tile (NN): one float4 along N per thread (8 k x 128 n)
    const int bn_k = tid >> 5;
    const int bn_n = (tid & 31) * 4;

    float acc[TM][TN];
#pragma unroll
    for (int i = 0; i < TM; i++)
#pragma unroll
        for (int j = 0; j < TN; j++) acc[i][j] = 0.0f;

    for (int k0 = 0; k0 < K; k0 += BK) {
        float4 av = *reinterpret_cast<const float4*>(
            &A[(long)(bm + a_m) * K + k0 + a_k]);
        As[a_k + 0][a_m] = av.x;
        As[a_k + 1][a_m] = av.y;
        As[a_k + 2][a_m] = av.z;
        As[a_k + 3][a_m] = av.w;

        if (NT) {
            float4 bv = *reinterpret_cast<const float4*>(
                &Bp[(long)(bn + bt_n) * K + k0 + bt_k]);
            Bs[bt_k + 0][bt_n] = bv.x;
            Bs[bt_k + 1][bt_n] = bv.y;
            Bs[bt_k + 2][bt_n] = bv.z;
            Bs[bt_k + 3][bt_n] = bv.w;
        } else {
            float4 bv = *reinterpret_cast<const float4*>(
                &Bp[(long)(k0 + bn_k) * N + bn + bn_n]);
            *reinterpret_cast<float4*>(&Bs[bn_k][bn_n]) = bv;
        }
        __syncthreads();

#pragma unroll
        for (int kk = 0; kk < BK; kk++) {
            float ar[TM], br[TN];
            *reinterpret_cast<float4*>(&ar[0]) =
                *reinterpret_cast<const float4*>(&As[kk][ty * TM]);
            *reinterpret_cast<float4*>(&ar[4]) =
                *reinterpret_cast<const float4*>(&As[kk][ty * TM + 4]);
            *reinterpret_cast<float4*>(&br[0]) =
                *reinterpret_cast<const float4*>(&Bs[kk][tx * TN]);
            *reinterpret_cast<float4*>(&br[4]) =
                *reinterpret_cast<const float4*>(&Bs[kk][tx * TN + 4]);
#pragma unroll
            for (int i = 0; i < TM; i++)
#pragma unroll
                for (int j = 0; j < TN; j++)
                    acc[i][j] = fmaf(ar[i], br[j], acc[i][j]);
        }
        __syncthreads();
    }

    float mk[TN];
    if (MASKED) {
        const float* mptr = maskg + (long)bz * sM;
#pragma unroll
        for (int j = 0; j < TN; j++) mk[j] = mptr[bn + tx * TN + j];
    }

#pragma unroll
    for (int i = 0; i < TM; i++) {
        long m = bm + ty * TM + i;
#pragma unroll
        for (int j = 0; j < TN; j += 4) {
            float4 v;
            v.x = acc[i][j + 0];
            v.y = acc[i][j + 1];
            v.z = acc[i][j + 2];
            v.w = acc[i][j + 3];
            if (MASKED) {
                v.x *= mk[j + 0];
                v.y *= mk[j + 1];
                v.z *= mk[j + 2];
                v.w *= mk[j + 3];
            }
            *reinterpret_cast<float4*>(&C[m * N + bn + tx * TN + j]) = v;
        }
    }
}

// ---------------------------------------------------------------------------
// Masked softmax over last dim (S=1024). One block (256 thr) per (b,t) row.
// x = e*m ; e = exp(x - max(x)) * m ; w = e / (sum(e) + 1e-6)
// ---------------------------------------------------------------------------
__global__ __launch_bounds__(256)
void masked_softmax_k(const float* __restrict__ energ,
                      const float* __restrict__ mask,
                      float* __restrict__ wout)
{
    const int row = blockIdx.x;         // b*TRG + t
    const int b = row >> 9;             // row / TRG_
    const float4* xr = reinterpret_cast<const float4*>(energ + (long)row * SRC_);
    const float4* mr = reinterpret_cast<const float4*>(mask + (long)b * SRC_);
    float4* wr = reinterpret_cast<float4*>(wout + (long)row * SRC_);
    const int t = threadIdx.x;          // SRC_/4 = 256 float4s

    float4 xv = xr[t];
    float4 mv = mr[t];
    xv.x *= mv.x; xv.y *= mv.y; xv.z *= mv.z; xv.w *= mv.w;

    float lmax = fmaxf(fmaxf(xv.x, xv.y), fmaxf(xv.z, xv.w));
#pragma unroll
    for (int o = 16; o; o >>= 1)
        lmax = fmaxf(lmax, __shfl_xor_sync(0xffffffffu, lmax, o));

    __shared__ float redm[8];
    __shared__ float reds[8];
    if ((t & 31) == 0) redm[t >> 5] = lmax;
    __syncthreads();
    float bmax = fmaxf(fmaxf(fmaxf(redm[0], redm[1]), fmaxf(redm[2], redm[3])),
                       fmaxf(fmaxf(redm[4], redm[5]), fmaxf(redm[6], redm[7])));

    float4 ev;
    ev.x = expf(xv.x - bmax) * mv.x;
    ev.y = expf(xv.y - bmax) * mv.y;
    ev.z = expf(xv.z - bmax) * mv.z;
    ev.w = expf(xv.w - bmax) * mv.w;

    float lsum = ev.x + ev.y + ev.z + ev.w;
#pragma unroll
    for (int o = 16; o; o >>= 1)
        lsum += __shfl_xor_sync(0xffffffffu, lsum, o);
    if ((t & 31) == 0) reds[t >> 5] = lsum;
    __syncthreads();
    float bsum = reds[0] + reds[1] + reds[2] + reds[3] +
                 reds[4] + reds[5] + reds[6] + reds[7];

    float inv = 1.0f / (bsum + 1e-6f);
    ev.x *= inv; ev.y *= inv; ev.z *= inv; ev.w *= inv;
    wr[t] = ev;
}

extern "C" void kernel_launch(void* const* d_in, const int* in_sizes, int n_in,
                              void* d_out, int out_size)
{
    const float* hidden  = (const float*)d_in[0];   // (B, TRG, TRGD)
    const float* enc_out = (const float*)d_in[1];   // (B, SRC, ENC)
    const float* enc_val = (const float*)d_in[2];   // (B, SRC, TRGD)
    const float* mask    = (const float*)d_in[3];   // (B, SRC)
    const float* W       = (const float*)d_in[4];   // (TRGD, ENC)

    float* out      = (float*)d_out;
    float* context  = out;                                    // (B, TRG, TRGD)
    float* weights  = out + (long)B_ * TRG_ * SRC_;           // (B, TRG, SRC)
    float* energies = out + 2L  * B_ * TRG_ * SRC_;           // (B, TRG, SRC)

    float* Hp = nullptr;
    cudaGetSymbolAddress((void**)&Hp, g_Hp);

    // 1) H' = hidden @ W : (B*TRG, TRGD) x (TRGD, ENC) -> (B*TRG, ENC), NN
    {
        dim3 grid(ENC_ / 128, (B_ * TRG_) / 128, 1);
        sgemm128<false, false><<<grid, 256>>>(
            hidden, W, Hp, nullptr,
            B_ * TRG_, ENC_, TRGD_, 0, 0, 0, 0);
    }

    // 2) energies[b] = (H'[b] @ enc_out[b]^T) * mask[b]  : NT, masked
    {
        dim3 grid(SRC_ / 128, TRG_ / 128, B_);
        sgemm128<true, true><<<grid, 256>>>(
            Hp, enc_out, energies, mask,
            TRG_, SRC_, ENC_,
            (long)TRG_ * ENC_, (long)SRC_ * ENC_, (long)TRG_ * SRC_, (long)SRC_);
    }

    // 3) masked softmax -> attn_weights
    masked_softmax_k<<<B_ * TRG_, 256>>>(energies, mask, weights);

    // 4) context[b] = weights[b] @ enc_val[b] : NN
    {
        dim3 grid(TRGD_ / 128, TRG_ / 128, B_);
        sgemm128<false, false><<<grid, 256>>>(
            weights, enc_val, context, nullptr,
            TRG_, TRGD_, SRC_,
            (long)TRG_ * SRC_, (long)SRC_ * TRGD_, (long)TRG_ * TRGD_, 0);
    }
}

// round 4
// speedup vs baseline: 1.3569x; 1.3569x over previous
#include <cuda_runtime.h>
#include <cstdint>

#define B_    16
#define TRG_  512
#define SRC_  1024
#define ENC_  1024
#define TRGD_ 1024

// ---------------- scratch (device globals; no allocs allowed) ----------------
__device__ float g_Hp  [(long)B_ * TRG_ * ENC_];    // hidden@W
__device__ float g_Wt  [(long)TRGD_ * ENC_];        // Wt[e,d] = W[d,e]
__device__ float g_EvT [(long)B_ * TRGD_ * SRC_];   // EvT[b][d,s] = ev[b][s,d]

// ---------------- helpers ----------------
__device__ __forceinline__ uint32_t s2u(const void* p) {
    uint32_t a;
    asm("{ .reg .u64 t; cvta.to.shared.u64 t, %1; cvt.u32.u64 %0, t; }"
        : "=r"(a) : "l"(p));
    return a;
}
__device__ __forceinline__ void tf32split(float v, uint32_t& hi, uint32_t& lo) {
    uint32_t h;
    asm("cvt.rna.tf32.f32 %0, %1;" : "=r"(h) : "f"(v));
    float r = v - __uint_as_float(h);
    uint32_t l;
    asm("cvt.rna.tf32.f32 %0, %1;" : "=r"(l) : "f"(r));
    hi = h; lo = l;
}
__device__ __forceinline__ void cp16(uint32_t d, const void* s) {
    asm volatile("cp.async.cg.shared.global [%0], [%1], 16;" :: "r"(d), "l"(s));
}
#define CP_COMMIT() asm volatile("cp.async.commit_group;" ::: "memory")

#define MMA_TF32(acc, a0, a1, a2, a3, b0, b1) \
    asm volatile( \
        "mma.sync.aligned.m16n8k8.row.col.f32.tf32.tf32.f32 " \
        "{%0,%1,%2,%3}, {%4,%5,%6,%7}, {%8,%9}, {%0,%1,%2,%3};" \
        : "+f"((acc)[0]), "+f"((acc)[1]), "+f"((acc)[2]), "+f"((acc)[3]) \
        : "r"(a0), "r"(a1), "r"(a2), "r"(a3), "r"(b0), "r"(b1))

// ---------------------------------------------------------------------------
// 3xTF32 tensor-core GEMM:  D[m,n] = sum_k A[m,k] * B[n,k]   (both K-major)
// BM=BN=128, BK=32, 3-stage cp.async, 256 threads, warp tile 32x64,
// hi/lo operand split -> fp32-accurate. Optional column-mask on output.
// ---------------------------------------------------------------------------
template<bool MASKED>
__global__ __launch_bounds__(256)
void gemm_mma(const float* __restrict__ Ag, const float* __restrict__ Bg,
              float* __restrict__ Cg, const float* __restrict__ maskg,
              int M, int N, int K, long sA, long sB, long sC)
{
    constexpr int BM = 128, BN = 128, BK = 32;
    constexpr int LDT = BK + 4;             // padded row stride (floats)
    constexpr int STAGE_FLOATS = 2 * BM * LDT;

    extern __shared__ float sm[];

    const int tid  = threadIdx.x;
    const int wid  = tid >> 5, lane = tid & 31;
    const int wy   = wid >> 1, wx = wid & 1;      // 4 x 2 warp grid
    const int bz   = blockIdx.z;
    const int bm   = blockIdx.y * BM, bn = blockIdx.x * BN;

    const float* A  = Ag + (long)bz * sA + (long)bm * K;
    const float* Bp = Bg + (long)bz * sB + (long)bn * K;
    float*       C  = Cg + (long)bz * sC;

    auto load_stage = [&](int s, int kc) {
        float* as = sm + s * STAGE_FLOATS;
        float* bs = as + BM * LDT;
        const int k0 = kc * BK;
#pragma unroll
        for (int i = 0; i < 4; i++) {
            int id = tid + 256 * i;
            int row = id >> 3, ch = id & 7;
            cp16(s2u(as + row * LDT + ch * 4), A + (long)row * K + k0 + ch * 4);
        }
#pragma unroll
        for (int i = 0; i < 4; i++) {
            int id = tid + 256 * i;
            int row = id >> 3, ch = id & 7;
            cp16(s2u(bs + row * LDT + ch * 4), Bp + (long)row * K + k0 + ch * 4);
        }
    };

    float acc[2][8][4];
#pragma unroll
    for (int i = 0; i < 2; i++)
#pragma unroll
        for (int j = 0; j < 8; j++)
#pragma unroll
            for (int v = 0; v < 4; v++) acc[i][j][v] = 0.0f;

    const int nch = K / BK;
    load_stage(0, 0); CP_COMMIT();
    load_stage(1, 1); CP_COMMIT();

    const int r0 = wy * 32 + (lane >> 2);
    const int n0 = wx * 64 + (lane >> 2);
    const int cK = lane & 3;

    for (int kc = 0; kc < nch; kc++) {
        asm volatile("cp.async.wait_group 1;" ::: "memory");
        __syncthreads();
        if (kc + 2 < nch) load_stage((kc + 2) % 3, kc + 2);
        CP_COMMIT();

        const float* as = sm + (kc % 3) * STAGE_FLOATS;
        const float* bs = as + BM * LDT;

#pragma unroll
        for (int ks = 0; ks < 4; ks++) {
            const int kk = ks * 8 + cK;
            uint32_t ah[2][4], al[2][4];
#pragma unroll
            for (int i = 0; i < 2; i++) {
                const float* base = as + (r0 + i * 16) * LDT + kk;
                tf32split(base[0],           ah[i][0], al[i][0]);
                tf32split(base[8 * LDT],     ah[i][1], al[i][1]);
                tf32split(base[4],           ah[i][2], al[i][2]);
                tf32split(base[8 * LDT + 4], ah[i][3], al[i][3]);
            }
#pragma unroll
            for (int j = 0; j < 8; j++) {
                const float* base = bs + (n0 + j * 8) * LDT + kk;
                uint32_t bh0, bl0, bh1, bl1;
                tf32split(base[0], bh0, bl0);
                tf32split(base[4], bh1, bl1);
#pragma unroll
                for (int i = 0; i < 2; i++) {
                    MMA_TF32(acc[i][j], ah[i][0], ah[i][1], ah[i][2], ah[i][3], bh0, bh1);
                    MMA_TF32(acc[i][j], ah[i][0], ah[i][1], ah[i][2], ah[i][3], bl0, bl1);
                    MMA_TF32(acc[i][j], al[i][0], al[i][1], al[i][2], al[i][3], bh0, bh1);
                }
            }
        }
    }

    // epilogue: direct register -> gmem (float2 stores)
#pragma unroll
    for (int i = 0; i < 2; i++) {
        const int row = bm + wy * 32 + i * 16 + (lane >> 2);
#pragma unroll
        for (int j = 0; j < 8; j++) {
            const int col = bn + wx * 64 + j * 8 + (lane & 3) * 2;
            float m0 = 1.0f, m1 = 1.0f;
            if (MASKED) {
                m0 = maskg[(long)bz * N + col];
                m1 = maskg[(long)bz * N + col + 1];
            }
            float2 p01, p23;
            p01.x = acc[i][j][0] * m0; p01.y = acc[i][j][1] * m1;
            p23.x = acc[i][j][2] * m0; p23.y = acc[i][j][3] * m1;
            *reinterpret_cast<float2*>(&C[(long)row * N + col]) = p01;
            *reinterpret_cast<float2*>(&C[(long)(row + 8) * N + col]) = p23;
        }
    }
}

// ---------------- batched transpose ----------------
__global__ __launch_bounds__(256)
void transpose_k(const float* __restrict__ in, float* __restrict__ out, int R, int C)
{
    __shared__ float t[32][33];
    long base = (long)blockIdx.z * R * C;
    int r0 = blockIdx.y * 32, c0 = blockIdx.x * 32;
    int x = threadIdx.x, y = threadIdx.y;  // 32x8
    for (int i = 0; i < 32; i += 8)
        t[y + i][x] = in[base + (long)(r0 + y + i) * C + c0 + x];
    __syncthreads();
    for (int i = 0; i < 32; i += 8)
        out[base + (long)(c0 + y + i) * R + r0 + x] = t[x][y + i];
}

// ---------------- masked softmax over S=1024 ----------------
__global__ __launch_bounds__(256)
void masked_softmax_k(const float* __restrict__ energ, const float* __restrict__ mask,
                      float* __restrict__ wout)
{
    const int row = blockIdx.x;
    const int b = row >> 9;
    const float4* xr = reinterpret_cast<const float4*>(energ + (long)row * SRC_);
    const float4* mr = reinterpret_cast<const float4*>(mask + (long)b * SRC_);
    float4* wr = reinterpret_cast<float4*>(wout + (long)row * SRC_);
    const int t = threadIdx.x;

    float4 xv = xr[t];
    float4 mv = mr[t];
    xv.x *= mv.x; xv.y *= mv.y; xv.z *= mv.z; xv.w *= mv.w;

    float lmax = fmaxf(fmaxf(xv.x, xv.y), fmaxf(xv.z, xv.w));
#pragma unroll
    for (int o = 16; o; o >>= 1)
        lmax = fmaxf(lmax, __shfl_xor_sync(0xffffffffu, lmax, o));

    __shared__ float redm[8];
    __shared__ float reds[8];
    if ((t & 31) == 0) redm[t >> 5] = lmax;
    __syncthreads();
    float bmax = fmaxf(fmaxf(fmaxf(redm[0], redm[1]), fmaxf(redm[2], redm[3])),
                       fmaxf(fmaxf(redm[4], redm[5]), fmaxf(redm[6], redm[7])));

    float4 ev;
    ev.x = expf(xv.x - bmax) * mv.x;
    ev.y = expf(xv.y - bmax) * mv.y;
    ev.z = expf(xv.z - bmax) * mv.z;
    ev.w = expf(xv.w - bmax) * mv.w;

    float lsum = ev.x + ev.y + ev.z + ev.w;
#pragma unroll
    for (int o = 16; o; o >>= 1)
        lsum += __shfl_xor_sync(0xffffffffu, lsum, o);
    if ((t & 31) == 0) reds[t >> 5] = lsum;
    __syncthreads();
    float bsum = reds[0] + reds[1] + reds[2] + reds[3] +
                 reds[4] + reds[5] + reds[6] + reds[7];

    float inv = 1.0f / (bsum + 1e-6f);
    ev.x *= inv; ev.y *= inv; ev.z *= inv; ev.w *= inv;
    wr[t] = ev;
}

// ---------------- launch ----------------
extern "C" void kernel_launch(void* const* d_in, const int* in_sizes, int n_in,
                              void* d_out, int out_size)
{
    const float* hidden  = (const float*)d_in[0];   // (B, TRG, TRGD)
    const float* enc_out = (const float*)d_in[1];   // (B, SRC, ENC)
    const float* enc_val = (const float*)d_in[2];   // (B, SRC, TRGD)
    const float* mask    = (const float*)d_in[3];   // (B, SRC)
    const float* W       = (const float*)d_in[4];   // (TRGD, ENC)

    float* out      = (float*)d_out;
    float* context  = out;                           // (B, TRG, TRGD)
    float* weights  = out + (long)B_ * TRG_ * SRC_;  // (B, TRG, SRC)
    float* energies = out + 2L * B_ * TRG_ * SRC_;   // (B, TRG, SRC)

    float *Hp, *Wt, *EvT;
    cudaGetSymbolAddress((void**)&Hp,  g_Hp);
    cudaGetSymbolAddress((void**)&Wt,  g_Wt);
    cudaGetSymbolAddress((void**)&EvT, g_EvT);

    const size_t dyn = 3UL * 2 * 128 * 36 * 4;  // 110,592 B
    cudaFuncSetAttribute(gemm_mma<false>,
                         cudaFuncAttributeMaxDynamicSharedMemorySize, dyn);
    cudaFuncSetAttribute(gemm_mma<true>,
                         cudaFuncAttributeMaxDynamicSharedMemorySize, dyn);

    // Wt[e,d] = W[d,e]
    {
        dim3 grid(ENC_ / 32, TRGD_ / 32, 1);
        transpose_k<<<grid, dim3(32, 8)>>>(W, Wt, TRGD_, ENC_);
    }
    // EvT[b][d,s] = enc_val[b][s,d]
    {
        dim3 grid(TRGD_ / 32, SRC_ / 32, B_);
        transpose_k<<<grid, dim3(32, 8)>>>(enc_val, EvT, SRC_, TRGD_);
    }

    // 1) Hp = hidden @ W : M=8192, N=1024, K=1024
    {
        dim3 grid(ENC_ / 128, (B_ * TRG_) / 128, 1);
        gemm_mma<false><<<grid, 256, dyn>>>(
            hidden, Wt, Hp, nullptr, B_ * TRG_, ENC_, TRGD_, 0, 0, 0);
    }
    // 2) energies[b] = (Hp[b] @ enc_out[b]^T) * mask[b]
    {
        dim3 grid(SRC_ / 128, TRG_ / 128, B_);
        gemm_mma<true><<<grid, 256, dyn>>>(
            Hp, enc_out, energies, mask, TRG_, SRC_, ENC_,
            (long)TRG_ * ENC_, (long)SRC_ * ENC_, (long)TRG_ * SRC_);
    }
    // 3) masked softmax -> weights
    masked_softmax_k<<<B_ * TRG_, 256>>>(energies, mask, weights);

    // 4) context[b] = weights[b] @ enc_val[b]
    {
        dim3 grid(TRGD_ / 128, TRG_ / 128, B_);
        gemm_mma<false><<<grid, 256, dyn>>>(
            weights, EvT, context, nullptr, TRG_, TRGD_, SRC_,
            (long)TRG_ * SRC_, (long)TRGD_ * SRC_, (long)TRG_ * TRGD_);
    }
}

// round 5
// speedup vs baseline: 1.9750x; 1.4556x over previous
#include <cuda_runtime.h>
#include <cstdint>

#define B_    16
#define TRG_  512
#define SRC_  1024
#define ENC_  1024
#define TRGD_ 1024

// ---------------- scratch (device globals; no allocs allowed) ----------------
__device__ float g_Hp  [(long)B_ * TRG_ * ENC_];    // hidden@W
__device__ float g_Wt  [(long)TRGD_ * ENC_];        // Wt[e,d] = W[d,e]
__device__ float g_EvT [(long)B_ * TRGD_ * SRC_];   // EvT[b][d,s] = ev[b][s,d]

// ---------------- helpers ----------------
__device__ __forceinline__ uint32_t s2u(const void* p) {
    uint32_t a;
    asm("{ .reg .u64 t; cvta.to.shared.u64 t, %1; cvt.u32.u64 %0, t; }"
        : "=r"(a) : "l"(p));
    return a;
}
// lo such that v = trunc_tf32(v) + lo exactly (HW truncates MMA operands to 19 bits)
__device__ __forceinline__ uint32_t tf32lo(float v) {
    uint32_t h = __float_as_uint(v) & 0xFFFFE000u;
    return __float_as_uint(v - __uint_as_float(h));
}
__device__ __forceinline__ uint32_t tf32rna(float v) {
    uint32_t o;
    asm("cvt.rna.tf32.f32 %0, %1;" : "=r"(o) : "f"(v));
    return o;
}
__device__ __forceinline__ void cp16(uint32_t d, const void* s) {
    asm volatile("cp.async.cg.shared.global [%0], [%1], 16;" :: "r"(d), "l"(s));
}
#define CP_COMMIT() asm volatile("cp.async.commit_group;" ::: "memory")

#define MMA_TF32(acc, a0, a1, a2, a3, b0, b1) \
    asm volatile( \
        "mma.sync.aligned.m16n8k8.row.col.f32.tf32.tf32.f32 " \
        "{%0,%1,%2,%3}, {%4,%5,%6,%7}, {%8,%9}, {%0,%1,%2,%3};" \
        : "+f"((acc)[0]), "+f"((acc)[1]), "+f"((acc)[2]), "+f"((acc)[3]) \
        : "r"(a0), "r"(a1), "r"(a2), "r"(a3), "r"(b0), "r"(b1))

// ---------------------------------------------------------------------------
// TF32 tensor-core GEMM:  D[m,n] = sum_k A[m,k] * B[n,k]   (both K-major)
// BM=BN=128, BK=32, 3-stage cp.async, 256 threads (4x2 warps, 32x64 tiles).
// PASSES=3: hi=raw bits (HW-truncated) + lo compensation -> fp32 accuracy.
// PASSES=1: rna-rounded single tf32 pass (for the final weights@value GEMM).
// ---------------------------------------------------------------------------
template<bool MASKED, int PASSES>
__global__ __launch_bounds__(256, 2)
void gemm_mma(const float* __restrict__ Ag, const float* __restrict__ Bg,
              float* __restrict__ Cg, const float* __restrict__ maskg,
              int M, int N, int K, long sA, long sB, long sC)
{
    constexpr int BM = 128, BN = 128, BK = 32;
    constexpr int LDT = BK + 4;
    constexpr int STAGE_FLOATS = 2 * BM * LDT;

    extern __shared__ float sm[];

    const int tid  = threadIdx.x;
    const int wid  = tid >> 5, lane = tid & 31;
    const int wy   = wid >> 1, wx = wid & 1;
    const int bz   = blockIdx.z;
    const int bm   = blockIdx.y * BM, bn = blockIdx.x * BN;

    const float* A  = Ag + (long)bz * sA + (long)bm * K;
    const float* Bp = Bg + (long)bz * sB + (long)bn * K;
    float*       C  = Cg + (long)bz * sC;

    auto load_stage = [&](int s, int kc) {
        float* as = sm + s * STAGE_FLOATS;
        float* bs = as + BM * LDT;
        const int k0 = kc * BK;
#pragma unroll
        for (int i = 0; i < 4; i++) {
            int id = tid + 256 * i;
            int row = id >> 3, ch = id & 7;
            cp16(s2u(as + row * LDT + ch * 4), A + (long)row * K + k0 + ch * 4);
        }
#pragma unroll
        for (int i = 0; i < 4; i++) {
            int id = tid + 256 * i;
            int row = id >> 3, ch = id & 7;
            cp16(s2u(bs + row * LDT + ch * 4), Bp + (long)row * K + k0 + ch * 4);
        }
    };

    float acc[2][8][4];
#pragma unroll
    for (int i = 0; i < 2; i++)
#pragma unroll
        for (int j = 0; j < 8; j++)
#pragma unroll
            for (int v = 0; v < 4; v++) acc[i][j][v] = 0.0f;

    const int nch = K / BK;
    load_stage(0, 0); CP_COMMIT();
    load_stage(1, 1); CP_COMMIT();

    const int r0 = wy * 32 + (lane >> 2);
    const int n0 = wx * 64 + (lane >> 2);
    const int cK = lane & 3;

    for (int kc = 0; kc < nch; kc++) {
        asm volatile("cp.async.wait_group 1;" ::: "memory");
        __syncthreads();
        if (kc + 2 < nch) load_stage((kc + 2) % 3, kc + 2);
        CP_COMMIT();

        const float* as = sm + (kc % 3) * STAGE_FLOATS;
        const float* bs = as + BM * LDT;

#pragma unroll
        for (int ks = 0; ks < 4; ks++) {
            const int kk = ks * 8 + cK;

            if (PASSES == 3) {
                uint32_t ah[2][4], al[2][4];
#pragma unroll
                for (int i = 0; i < 2; i++) {
                    const float* base = as + (r0 + i * 16) * LDT + kk;
                    float v0 = base[0], v1 = base[8 * LDT];
                    float v2 = base[4], v3 = base[8 * LDT + 4];
                    ah[i][0] = __float_as_uint(v0); al[i][0] = tf32lo(v0);
                    ah[i][1] = __float_as_uint(v1); al[i][1] = tf32lo(v1);
                    ah[i][2] = __float_as_uint(v2); al[i][2] = tf32lo(v2);
                    ah[i][3] = __float_as_uint(v3); al[i][3] = tf32lo(v3);
                }
#pragma unroll
                for (int j = 0; j < 8; j++) {
                    const float* base = bs + (n0 + j * 8) * LDT + kk;
                    float w0 = base[0], w1 = base[4];
                    uint32_t bh0 = __float_as_uint(w0), bl0 = tf32lo(w0);
                    uint32_t bh1 = __float_as_uint(w1), bl1 = tf32lo(w1);
#pragma unroll
                    for (int i = 0; i < 2; i++) {
                        MMA_TF32(acc[i][j], ah[i][0], ah[i][1], ah[i][2], ah[i][3], bh0, bh1);
                        MMA_TF32(acc[i][j], ah[i][0], ah[i][1], ah[i][2], ah[i][3], bl0, bl1);
                        MMA_TF32(acc[i][j], al[i][0], al[i][1], al[i][2], al[i][3], bh0, bh1);
                    }
                }
            } else {
                uint32_t ar[2][4];
#pragma unroll
                for (int i = 0; i < 2; i++) {
                    const float* base = as + (r0 + i * 16) * LDT + kk;
                    ar[i][0] = tf32rna(base[0]);
                    ar[i][1] = tf32rna(base[8 * LDT]);
                    ar[i][2] = tf32rna(base[4]);
                    ar[i][3] = tf32rna(base[8 * LDT + 4]);
                }
#pragma unroll
                for (int j = 0; j < 8; j++) {
                    const float* base = bs + (n0 + j * 8) * LDT + kk;
                    uint32_t b0 = tf32rna(base[0]);
                    uint32_t b1 = tf32rna(base[4]);
#pragma unroll
                    for (int i = 0; i < 2; i++)
                        MMA_TF32(acc[i][j], ar[i][0], ar[i][1], ar[i][2], ar[i][3], b0, b1);
                }
            }
        }
    }

    // epilogue: direct register -> gmem (float2 stores)
#pragma unroll
    for (int i = 0; i < 2; i++) {
        const int row = bm + wy * 32 + i * 16 + (lane >> 2);
#pragma unroll
        for (int j = 0; j < 8; j++) {
            const int col = bn + wx * 64 + j * 8 + (lane & 3) * 2;
            float m0 = 1.0f, m1 = 1.0f;
            if (MASKED) {
                m0 = maskg[(long)bz * N + col];
                m1 = maskg[(long)bz * N + col + 1];
            }
            float2 p01, p23;
            p01.x = acc[i][j][0] * m0; p01.y = acc[i][j][1] * m1;
            p23.x = acc[i][j][2] * m0; p23.y = acc[i][j][3] * m1;
            *reinterpret_cast<float2*>(&C[(long)row * N + col]) = p01;
            *reinterpret_cast<float2*>(&C[(long)(row + 8) * N + col]) = p23;
        }
    }
}

// ---------------- batched transpose ----------------
__global__ __launch_bounds__(256)
void transpose_k(const float* __restrict__ in, float* __restrict__ out, int R, int C)
{
    __shared__ float t[32][33];
    long base = (long)blockIdx.z * R * C;
    int r0 = blockIdx.y * 32, c0 = blockIdx.x * 32;
    int x = threadIdx.x, y = threadIdx.y;  // 32x8
    for (int i = 0; i < 32; i += 8)
        t[y + i][x] = in[base + (long)(r0 + y + i) * C + c0 + x];
    __syncthreads();
    for (int i = 0; i < 32; i += 8)
        out[base + (long)(c0 + y + i) * R + r0 + x] = t[x][y + i];
}

// ---------------- masked softmax over S=1024 ----------------
__global__ __launch_bounds__(256)
void masked_softmax_k(const float* __restrict__ energ, const float* __restrict__ mask,
                      float* __restrict__ wout)
{
    const int row = blockIdx.x;
    const int b = row >> 9;
    const float4* xr = reinterpret_cast<const float4*>(energ + (long)row * SRC_);
    const float4* mr = reinterpret_cast<const float4*>(mask + (long)b * SRC_);
    float4* wr = reinterpret_cast<float4*>(wout + (long)row * SRC_);
    const int t = threadIdx.x;

    float4 xv = xr[t];
    float4 mv = mr[t];
    xv.x *= mv.x; xv.y *= mv.y; xv.z *= mv.z; xv.w *= mv.w;

    float lmax = fmaxf(fmaxf(xv.x, xv.y), fmaxf(xv.z, xv.w));
#pragma unroll
    for (int o = 16; o; o >>= 1)
        lmax = fmaxf(lmax, __shfl_xor_sync(0xffffffffu, lmax, o));

    __shared__ float redm[8];
    __shared__ float reds[8];
    if ((t & 31) == 0) redm[t >> 5] = lmax;
    __syncthreads();
    float bmax = fmaxf(fmaxf(fmaxf(redm[0], redm[1]), fmaxf(redm[2], redm[3])),
                       fmaxf(fmaxf(redm[4], redm[5]), fmaxf(redm[6], redm[7])));

    float4 ev;
    ev.x = expf(xv.x - bmax) * mv.x;
    ev.y = expf(xv.y - bmax) * mv.y;
    ev.z = expf(xv.z - bmax) * mv.z;
    ev.w = expf(xv.w - bmax) * mv.w;

    float lsum = ev.x + ev.y + ev.z + ev.w;
#pragma unroll
    for (int o = 16; o; o >>= 1)
        lsum += __shfl_xor_sync(0xffffffffu, lsum, o);
    if ((t & 31) == 0) reds[t >> 5] = lsum;
    __syncthreads();
    float bsum = reds[0] + reds[1] + reds[2] + reds[3] +
                 reds[4] + reds[5] + reds[6] + reds[7];

    float inv = 1.0f / (bsum + 1e-6f);
    ev.x *= inv; ev.y *= inv; ev.z *= inv; ev.w *= inv;
    wr[t] = ev;
}

// ---------------- launch ----------------
extern "C" void kernel_launch(void* const* d_in, const int* in_sizes, int n_in,
                              void* d_out, int out_size)
{
    const float* hidden  = (const float*)d_in[0];   // (B, TRG, TRGD)
    const float* enc_out = (const float*)d_in[1];   // (B, SRC, ENC)
    const float* enc_val = (const float*)d_in[2];   // (B, SRC, TRGD)
    const float* mask    = (const float*)d_in[3];   // (B, SRC)
    const float* W       = (const float*)d_in[4];   // (TRGD, ENC)

    float* out      = (float*)d_out;
    float* context  = out;                           // (B, TRG, TRGD)
    float* weights  = out + (long)B_ * TRG_ * SRC_;  // (B, TRG, SRC)
    float* energies = out + 2L * B_ * TRG_ * SRC_;   // (B, TRG, SRC)

    float *Hp, *Wt, *EvT;
    cudaGetSymbolAddress((void**)&Hp,  g_Hp);
    cudaGetSymbolAddress((void**)&Wt,  g_Wt);
    cudaGetSymbolAddress((void**)&EvT, g_EvT);

    const size_t dyn = 3UL * 2 * 128 * 36 * 4;  // 110,592 B
    cudaFuncSetAttribute(gemm_mma<false, 3>,
                         cudaFuncAttributeMaxDynamicSharedMemorySize, dyn);
    cudaFuncSetAttribute(gemm_mma<true, 3>,
                         cudaFuncAttributeMaxDynamicSharedMemorySize, dyn);
    cudaFuncSetAttribute(gemm_mma<false, 1>,
                         cudaFuncAttributeMaxDynamicSharedMemorySize, dyn);

    // Wt[e,d] = W[d,e]
    {
        dim3 grid(ENC_ / 32, TRGD_ / 32, 1);
        transpose_k<<<grid, dim3(32, 8)>>>(W, Wt, TRGD_, ENC_);
    }
    // EvT[b][d,s] = enc_val[b][s,d]
    {
        dim3 grid(TRGD_ / 32, SRC_ / 32, B_);
        transpose_k<<<grid, dim3(32, 8)>>>(enc_val, EvT, SRC_, TRGD_);
    }

    // 1) Hp = hidden @ W : M=8192, N=1024, K=1024  (3xTF32)
    {
        dim3 grid(ENC_ / 128, (B_ * TRG_) / 128, 1);
        gemm_mma<false, 3><<<grid, 256, dyn>>>(
            hidden, Wt, Hp, nullptr, B_ * TRG_, ENC_, TRGD_, 0, 0, 0);
    }
    // 2) energies[b] = (Hp[b] @ enc_out[b]^T) * mask[b]  (3xTF32)
    {
        dim3 grid(SRC_ / 128, TRG_ / 128, B_);
        gemm_mma<true, 3><<<grid, 256, dyn>>>(
            Hp, enc_out, energies, mask, TRG_, SRC_, ENC_,
            (long)TRG_ * ENC_, (long)SRC_ * ENC_, (long)TRG_ * SRC_);
    }
    // 3) masked softmax -> weights
    masked_softmax_k<<<B_ * TRG_, 256>>>(energies, mask, weights);

    // 4) context[b] = weights[b] @ enc_val[b]  (1xTF32 rna)
    {
        dim3 grid(TRGD_ / 128, TRG_ / 128, B_);
        gemm_mma<false, 1><<<grid, 256, dyn>>>(
            weights, EvT, context, nullptr, TRG_, TRGD_, SRC_,
            (long)TRG_ * SRC_, (long)TRGD_ * SRC_, (long)TRG_ * TRGD_);
    }
}

// round 6
// speedup vs baseline: 2.0785x; 1.0524x over previous
#include <cuda_runtime.h>
#include <cstdint>

#define B_    16
#define TRG_  512
#define SRC_  1024
#define ENC_  1024
#define TRGD_ 1024

// ---------------- scratch (device globals; no allocs allowed) ----------------
__device__ float g_Hp[(long)B_ * TRG_ * ENC_];      // hidden@W

// ---------------- helpers ----------------
__device__ __forceinline__ uint32_t s2u(const void* p) {
    uint32_t a;
    asm("{ .reg .u64 t; cvta.to.shared.u64 t, %1; cvt.u32.u64 %0, t; }"
        : "=r"(a) : "l"(p));
    return a;
}
// lo such that v = trunc_tf32(v) + lo exactly (HW truncates MMA operands to 19 bits)
__device__ __forceinline__ uint32_t tf32lo(float v) {
    uint32_t h = __float_as_uint(v) & 0xFFFFE000u;
    return __float_as_uint(v - __uint_as_float(h));
}
__device__ __forceinline__ uint32_t tf32rna(float v) {
    uint32_t o;
    asm("cvt.rna.tf32.f32 %0, %1;" : "=r"(o) : "f"(v));
    return o;
}
__device__ __forceinline__ void cp16(uint32_t d, const void* s) {
    asm volatile("cp.async.cg.shared.global [%0], [%1], 16;" :: "r"(d), "l"(s));
}
#define CP_COMMIT() asm volatile("cp.async.commit_group;" ::: "memory")

#define MMA_TF32(acc, a0, a1, a2, a3, b0, b1) \
    asm volatile( \
        "mma.sync.aligned.m16n8k8.row.col.f32.tf32.tf32.f32 " \
        "{%0,%1,%2,%3}, {%4,%5,%6,%7}, {%8,%9}, {%0,%1,%2,%3};" \
        : "+f"((acc)[0]), "+f"((acc)[1]), "+f"((acc)[2]), "+f"((acc)[3]) \
        : "r"(a0), "r"(a1), "r"(a2), "r"(a3), "r"(b0), "r"(b1))

// ---------------------------------------------------------------------------
// TF32 tensor-core GEMM:  D[m,n] = sum_k A[m,k] * B[n,k]
// A is K-major. B layout templated:
//   BNN=false: B K-major (rows n, k contiguous)  -> smem Bs[n][k], LDT=36
//   BNN=true : B N-major (rows k, n contiguous)  -> smem Bs[k][n], LDN=136
//              (fragment banks (lane&3)*8+(lane>>2): conflict-free)
// BM=BN=128, BK=32, 3-stage cp.async, 256 threads (4x2 warps, 32x64 tiles).
// PASSES=3: hi=raw bits (HW-truncated) + lo compensation -> fp32 accuracy.
// PASSES=1: rna-rounded single tf32 pass.
// ---------------------------------------------------------------------------
template<bool MASKED, int PASSES, bool BNN>
__global__ __launch_bounds__(256, 2)
void gemm_mma(const float* __restrict__ Ag, const float* __restrict__ Bg,
              float* __restrict__ Cg, const float* __restrict__ maskg,
              int M, int N, int K, long sA, long sB, long sC)
{
    constexpr int BM = 128, BN = 128, BK = 32;
    constexpr int LDT = BK + 4;    // A tile (and K-major B tile) row stride
    constexpr int LDN = BN + 8;    // NN B tile row stride (perfect frag banks)
    constexpr int STAGE_FLOATS = 2 * BM * LDT;   // covers both layouts

    extern __shared__ float sm[];

    const int tid  = threadIdx.x;
    const int wid  = tid >> 5, lane = tid & 31;
    const int wy   = wid >> 1, wx = wid & 1;
    const int bz   = blockIdx.z;
    const int bm   = blockIdx.y * BM, bn = blockIdx.x * BN;

    const float* A  = Ag + (long)bz * sA + (long)bm * K;
    const float* Bp = BNN ? (Bg + (long)bz * sB + bn)
                          : (Bg + (long)bz * sB + (long)bn * K);
    float*       C  = Cg + (long)bz * sC;

    auto load_stage = [&](int s, int kc) {
        float* as = sm + s * STAGE_FLOATS;
        float* bs = as + BM * LDT;
        const int k0 = kc * BK;
#pragma unroll
        for (int i = 0; i < 4; i++) {
            int id = tid + 256 * i;
            int row = id >> 3, ch = id & 7;
            cp16(s2u(as + row * LDT + ch * 4), A + (long)row * K + k0 + ch * 4);
        }
        if (BNN) {
#pragma unroll
            for (int i = 0; i < 4; i++) {
                int id = tid + 256 * i;
                int r = id >> 5, c = (id & 31) * 4;
                cp16(s2u(bs + r * LDN + c), Bp + (long)(k0 + r) * N + c);
            }
        } else {
#pragma unroll
            for (int i = 0; i < 4; i++) {
                int id = tid + 256 * i;
                int row = id >> 3, ch = id & 7;
                cp16(s2u(bs + row * LDT + ch * 4), Bp + (long)row * K + k0 + ch * 4);
            }
        }
    };

    float acc[2][8][4];
#pragma unroll
    for (int i = 0; i < 2; i++)
#pragma unroll
        for (int j = 0; j < 8; j++)
#pragma unroll
            for (int v = 0; v < 4; v++) acc[i][j][v] = 0.0f;

    const int nch = K / BK;
    load_stage(0, 0); CP_COMMIT();
    load_stage(1, 1); CP_COMMIT();

    const int r0 = wy * 32 + (lane >> 2);
    const int n0 = wx * 64 + (lane >> 2);
    const int cK = lane & 3;

    for (int kc = 0; kc < nch; kc++) {
        asm volatile("cp.async.wait_group 1;" ::: "memory");
        __syncthreads();
        if (kc + 2 < nch) load_stage((kc + 2) % 3, kc + 2);
        CP_COMMIT();

        const float* as = sm + (kc % 3) * STAGE_FLOATS;
        const float* bs = as + BM * LDT;

#pragma unroll
        for (int ks = 0; ks < 4; ks++) {
            const int kk = ks * 8 + cK;

            // load B fragment j into (bh, bl) [bl unused for PASSES==1]
            auto loadB = [&](int j, uint32_t* bh, uint32_t* bl) {
                float w0, w1;
                if (BNN) {
                    const float* base = bs + kk * LDN + n0 + j * 8;
                    w0 = base[0];
                    w1 = base[4 * LDN];
                } else {
                    const float* base = bs + (n0 + j * 8) * LDT + kk;
                    w0 = base[0];
                    w1 = base[4];
                }
                if (PASSES == 3) {
                    bh[0] = __float_as_uint(w0); bl[0] = tf32lo(w0);
                    bh[1] = __float_as_uint(w1); bl[1] = tf32lo(w1);
                } else {
                    bh[0] = tf32rna(w0);
                    bh[1] = tf32rna(w1);
                }
            };

            if (PASSES == 3) {
                uint32_t ah[2][4], al[2][4];
#pragma unroll
                for (int i = 0; i < 2; i++) {
                    const float* base = as + (r0 + i * 16) * LDT + kk;
                    float v0 = base[0], v1 = base[8 * LDT];
                    float v2 = base[4], v3 = base[8 * LDT + 4];
                    ah[i][0] = __float_as_uint(v0); al[i][0] = tf32lo(v0);
                    ah[i][1] = __float_as_uint(v1); al[i][1] = tf32lo(v1);
                    ah[i][2] = __float_as_uint(v2); al[i][2] = tf32lo(v2);
                    ah[i][3] = __float_as_uint(v3); al[i][3] = tf32lo(v3);
                }
                uint32_t bh0[2], bl0[2], bh1[2], bl1[2];
                loadB(0, bh0, bl0);
#pragma unroll
                for (int j = 0; j < 8; j++) {
                    uint32_t* bh = (j & 1) ? bh1 : bh0;
                    uint32_t* bl = (j & 1) ? bl1 : bl0;
                    if (j < 7) loadB(j + 1, (j & 1) ? bh0 : bh1,
                                             (j & 1) ? bl0 : bl1);
#pragma unroll
                    for (int i = 0; i < 2; i++) {
                        MMA_TF32(acc[i][j], ah[i][0], ah[i][1], ah[i][2], ah[i][3], bh[0], bh[1]);
                        MMA_TF32(acc[i][j], ah[i][0], ah[i][1], ah[i][2], ah[i][3], bl[0], bl[1]);
                        MMA_TF32(acc[i][j], al[i][0], al[i][1], al[i][2], al[i][3], bh[0], bh[1]);
                    }
                }
            } else {
                uint32_t ar[2][4];
#pragma unroll
                for (int i = 0; i < 2; i++) {
                    const float* base = as + (r0 + i * 16) * LDT + kk;
                    ar[i][0] = tf32rna(base[0]);
                    ar[i][1] = tf32rna(base[8 * LDT]);
                    ar[i][2] = tf32rna(base[4]);
                    ar[i][3] = tf32rna(base[8 * LDT + 4]);
                }
                uint32_t bh0[2], bh1[2];
                loadB(0, bh0, nullptr);
#pragma unroll
                for (int j = 0; j < 8; j++) {
                    uint32_t* bh = (j & 1) ? bh1 : bh0;
                    if (j < 7) loadB(j + 1, (j & 1) ? bh0 : bh1, nullptr);
#pragma unroll
                    for (int i = 0; i < 2; i++)
                        MMA_TF32(acc[i][j], ar[i][0], ar[i][1], ar[i][2], ar[i][3], bh[0], bh[1]);
                }
            }
        }
    }

    // epilogue: direct register -> gmem (float2 stores)
#pragma unroll
    for (int i = 0; i < 2; i++) {
        const int row = bm + wy * 32 + i * 16 + (lane >> 2);
#pragma unroll
        for (int j = 0; j < 8; j++) {
            const int col = bn + wx * 64 + j * 8 + (lane & 3) * 2;
            float m0 = 1.0f, m1 = 1.0f;
            if (MASKED) {
                m0 = maskg[(long)bz * N + col];
                m1 = maskg[(long)bz * N + col + 1];
            }
            float2 p01, p23;
            p01.x = acc[i][j][0] * m0; p01.y = acc[i][j][1] * m1;
            p23.x = acc[i][j][2] * m0; p23.y = acc[i][j][3] * m1;
            *reinterpret_cast<float2*>(&C[(long)row * N + col]) = p01;
            *reinterpret_cast<float2*>(&C[(long)(row + 8) * N + col]) = p23;
        }
    }
}

// ---------------- masked softmax over S=1024 ----------------
__global__ __launch_bounds__(256)
void masked_softmax_k(const float* __restrict__ energ, const float* __restrict__ mask,
                      float* __restrict__ wout)
{
    const int row = blockIdx.x;
    const int b = row >> 9;
    const float4* xr = reinterpret_cast<const float4*>(energ + (long)row * SRC_);
    const float4* mr = reinterpret_cast<const float4*>(mask + (long)b * SRC_);
    float4* wr = reinterpret_cast<float4*>(wout + (long)row * SRC_);
    const int t = threadIdx.x;

    float4 xv = xr[t];
    float4 mv = mr[t];
    xv.x *= mv.x; xv.y *= mv.y; xv.z *= mv.z; xv.w *= mv.w;

    float lmax = fmaxf(fmaxf(xv.x, xv.y), fmaxf(xv.z, xv.w));
#pragma unroll
    for (int o = 16; o; o >>= 1)
        lmax = fmaxf(lmax, __shfl_xor_sync(0xffffffffu, lmax, o));

    __shared__ float redm[8];
    __shared__ float reds[8];
    if ((t & 31) == 0) redm[t >> 5] = lmax;
    __syncthreads();
    float bmax = fmaxf(fmaxf(fmaxf(redm[0], redm[1]), fmaxf(redm[2], redm[3])),
                       fmaxf(fmaxf(redm[4], redm[5]), fmaxf(redm[6], redm[7])));

    float4 ev;
    ev.x = expf(xv.x - bmax) * mv.x;
    ev.y = expf(xv.y - bmax) * mv.y;
    ev.z = expf(xv.z - bmax) * mv.z;
    ev.w = expf(xv.w - bmax) * mv.w;

    float lsum = ev.x + ev.y + ev.z + ev.w;
#pragma unroll
    for (int o = 16; o; o >>= 1)
        lsum += __shfl_xor_sync(0xffffffffu, lsum, o);
    if ((t & 31) == 0) reds[t >> 5] = lsum;
    __syncthreads();
    float bsum = reds[0] + reds[1] + reds[2] + reds[3] +
                 reds[4] + reds[5] + reds[6] + reds[7];

    float inv = 1.0f / (bsum + 1e-6f);
    ev.x *= inv; ev.y *= inv; ev.z *= inv; ev.w *= inv;
    wr[t] = ev;
}

// ---------------- launch ----------------
extern "C" void kernel_launch(void* const* d_in, const int* in_sizes, int n_in,
                              void* d_out, int out_size)
{
    const float* hidden  = (const float*)d_in[0];   // (B, TRG, TRGD)
    const float* enc_out = (const float*)d_in[1];   // (B, SRC, ENC)
    const float* enc_val = (const float*)d_in[2];   // (B, SRC, TRGD)
    const float* mask    = (const float*)d_in[3];   // (B, SRC)
    const float* W       = (const float*)d_in[4];   // (TRGD, ENC)

    float* out      = (float*)d_out;
    float* context  = out;                           // (B, TRG, TRGD)
    float* weights  = out + (long)B_ * TRG_ * SRC_;  // (B, TRG, SRC)
    float* energies = out + 2L * B_ * TRG_ * SRC_;   // (B, TRG, SRC)

    float* Hp;
    cudaGetSymbolAddress((void**)&Hp, g_Hp);

    const size_t dyn = 3UL * 2 * 128 * 36 * 4;  // 110,592 B
    cudaFuncSetAttribute(gemm_mma<false, 3, true>,
                         cudaFuncAttributeMaxDynamicSharedMemorySize, dyn);
    cudaFuncSetAttribute(gemm_mma<true, 3, false>,
                         cudaFuncAttributeMaxDynamicSharedMemorySize, dyn);
    cudaFuncSetAttribute(gemm_mma<false, 1, true>,
                         cudaFuncAttributeMaxDynamicSharedMemorySize, dyn);

    // 1) Hp[t,e] = sum_d hidden[t,d] * W[d,e]  (B = W, NN layout; 3xTF32)
    {
        dim3 grid(ENC_ / 128, (B_ * TRG_) / 128, 1);
        gemm_mma<false, 3, true><<<grid, 256, dyn>>>(
            hidden, W, Hp, nullptr, B_ * TRG_, ENC_, TRGD_, 0, 0, 0);
    }
    // 2) energies[b] = (Hp[b] @ enc_out[b]^T) * mask[b]  (K-major B; 3xTF32)
    {
        dim3 grid(SRC_ / 128, TRG_ / 128, B_);
        gemm_mma<true, 3, false><<<grid, 256, dyn>>>(
            Hp, enc_out, energies, mask, TRG_, SRC_, ENC_,
            (long)TRG_ * ENC_, (long)SRC_ * ENC_, (long)TRG_ * SRC_);
    }
    // 3) masked softmax -> weights
    masked_softmax_k<<<B_ * TRG_, 256>>>(energies, mask, weights);

    // 4) context[b][t,d] = sum_s weights[b][t,s] * enc_val[b][s,d]
    //    (B = enc_val, NN layout; 1xTF32 rna)
    {
        dim3 grid(TRGD_ / 128, TRG_ / 128, B_);
        gemm_mma<false, 1, true><<<grid, 256, dyn>>>(
            weights, enc_val, context, nullptr, TRG_, TRGD_, SRC_,
            (long)TRG_ * SRC_, (long)SRC_ * TRGD_, (long)TRG_ * TRGD_);
    }
}